// round 4
// baseline (speedup 1.0000x reference)
#include <cuda_runtime.h>
#include <cstdint>

// Problem constants
#define B  8
#define N  4096
#define F  128
#define GS 1024

// Scratch
__device__ unsigned int       g_keys[B * N];  // monotone-mapped last-feature values
__device__ unsigned long long g_sel[B * GS];  // selected keys, unordered
__device__ int                g_idx[B * GS];  // final top-k indices, jax order

// ---------------------------------------------------------------------------
// Kernel 0: chip-wide extraction of x[:, :, F-1] -> monotone uint keys.
// ---------------------------------------------------------------------------
__global__ __launch_bounds__(256) void extract_kernel(const float* __restrict__ x)
{
    const int i = blockIdx.x * 256 + threadIdx.x;   // 0 .. B*N-1
    float v = x[(size_t)i * F + (F - 1)];
    unsigned int u = __float_as_uint(v);
    u = (u & 0x80000000u) ? ~u : (u | 0x80000000u); // bigger float -> bigger uint
    g_keys[i] = u;
}

// ---------------------------------------------------------------------------
// Kernel 1: per-batch exact threshold via MSB radix select + compaction.
// key = (monotone(v) << 12) | (4095 - i); top-1024 largest == jax top_k
// (value desc, tie -> smaller index). Keys are unique.
// ---------------------------------------------------------------------------
__global__ __launch_bounds__(512) void select_kernel()
{
    __shared__ unsigned long long sk[N];   // 32 KB
    __shared__ unsigned int hist[256];
    __shared__ unsigned int s_bin, s_above, s_cnt;

    const int b   = blockIdx.x;
    const int tid = threadIdx.x;

    #pragma unroll
    for (int l = 0; l < 8; ++l) {
        int i = tid + l * 512;
        unsigned int u = g_keys[b * N + i];
        sk[i] = ((unsigned long long)u << 12) | (unsigned int)(N - 1 - i);
    }
    if (tid == 0) s_cnt = 0;
    __syncthreads();

    unsigned long long prefix = 0, pmask = 0;
    unsigned int need = GS;

    #pragma unroll
    for (int pass = 0; pass < 6; ++pass) {
        const int          shift = (pass < 5) ? (36 - 8 * pass) : 0;
        const unsigned int dmask = (pass < 5) ? 0xFFu : 0xFu;

        if (tid < 256) hist[tid] = 0;
        __syncthreads();

        #pragma unroll
        for (int l = 0; l < 8; ++l) {
            unsigned long long k = sk[tid + l * 512];
            if ((k & pmask) == prefix)
                atomicAdd(&hist[(unsigned int)(k >> shift) & dmask], 1u);
        }
        __syncthreads();

        if (tid < 32) {
            unsigned int sum = 0;
            #pragma unroll
            for (int j = 0; j < 8; ++j) sum += hist[tid * 8 + j];
            unsigned int acc = sum;
            #pragma unroll
            for (int off = 1; off < 32; off <<= 1) {
                unsigned int t = __shfl_down_sync(0xFFFFFFFFu, acc, off);
                if (tid + off < 32) acc += t;
            }
            unsigned int running = acc - sum;   // strictly above my group
            #pragma unroll
            for (int j = 7; j >= 0; --j) {
                unsigned int c = hist[tid * 8 + j];
                if (running < need && need <= running + c) {
                    s_bin = (unsigned int)(tid * 8 + j);
                    s_above = running;
                }
                running += c;
            }
        }
        __syncthreads();

        prefix |= ((unsigned long long)s_bin) << shift;
        pmask  |= ((unsigned long long)dmask) << shift;
        need   -= s_above;
        __syncthreads();
    }
    // prefix == exact 1024th-largest key. Selected set: key >= prefix.

    #pragma unroll
    for (int l = 0; l < 8; ++l) {
        unsigned long long k = sk[tid + l * 512];
        if (k >= prefix) {
            unsigned int pos = atomicAdd(&s_cnt, 1u);
            g_sel[b * GS + pos] = k;
        }
    }
}

// ---------------------------------------------------------------------------
// Kernel 2: rank-by-count over the 1024 selected keys -> ordered indices.
// ---------------------------------------------------------------------------
__global__ __launch_bounds__(128) void rank_kernel()
{
    __shared__ unsigned long long sk[GS];  // 8 KB

    const int b   = blockIdx.x >> 3;
    const int c   = blockIdx.x & 7;
    const int tid = threadIdx.x;

    #pragma unroll
    for (int l = 0; l < GS / 128; ++l)
        sk[tid + l * 128] = g_sel[b * GS + tid + l * 128];
    __syncthreads();

    const unsigned long long mine = sk[c * 128 + tid];
    int rank = 0;
    #pragma unroll 8
    for (int j = 0; j < GS; ++j)
        rank += (sk[j] > mine);

    g_idx[b * GS + rank] = (N - 1) - (int)(mine & 0xFFFu);
}

// ---------------------------------------------------------------------------
// Kernel 3: 8 output rows per CTA, register-staged double buffer:
// while gathering row r from smem, row r+1's 16KB is in flight in registers.
// ---------------------------------------------------------------------------
__global__ __launch_bounds__(512) void gather_kernel(const float* __restrict__ A,
                                                     const float* __restrict__ x,
                                                     float* __restrict__ out)
{
    __shared__ float row[N];        // 16 KB
    __shared__ int   sidx[GS];      // 4 KB

    const int bi  = blockIdx.x;          // 0..1023
    const int b   = bi >> 7;             // 128 CTAs per batch
    const int i0  = (bi & 127) * 8;
    const int tid = threadIdx.x;

    #pragma unroll
    for (int t = tid; t < GS; t += 512) sidx[t] = g_idx[b * GS + t];
    __syncthreads();

    // Prologue: start loading row i0
    int ri = sidx[i0];
    const float4* arow = (const float4*)(A + ((size_t)b * N + ri) * N);
    float4 r0 = arow[tid];
    float4 r1 = arow[tid + 512];
    float4 xv;
    if (tid < F / 4) xv = ((const float4*)(x + ((size_t)b * N + ri) * F))[tid];

    float4* rowv = (float4*)row;

    #pragma unroll
    for (int r = 0; r < 8; ++r) {
        // Stage current row regs -> smem (stalls only on this row's LDGs)
        rowv[tid]       = r0;
        rowv[tid + 512] = r1;
        // xg row for current row
        if (tid < F / 4) {
            ((float4*)(out + (size_t)B * GS * GS
                           + ((size_t)b * GS + i0 + r) * F))[tid] = xv;
        }
        __syncthreads();

        // Prefetch next row into regs (overlaps with gather below)
        if (r < 7) {
            int rn = sidx[i0 + r + 1];
            const float4* an = (const float4*)(A + ((size_t)b * N + rn) * N);
            r0 = an[tid];
            r1 = an[tid + 512];
            if (tid < F / 4) xv = ((const float4*)(x + ((size_t)b * N + rn) * F))[tid];
        }

        // Gather selected columns -> At2 row
        float* orow = out + ((size_t)b * GS + i0 + r) * GS;
        orow[tid]       = row[sidx[tid]];
        orow[tid + 512] = row[sidx[tid + 512]];
        __syncthreads();
    }
}

// ---------------------------------------------------------------------------
extern "C" void kernel_launch(void* const* d_in, const int* in_sizes, int n_in,
                              void* d_out, int out_size)
{
    const float* A = (const float*)d_in[0];  // (8,4096,4096) f32
    const float* x = (const float*)d_in[1];  // (8,4096,128)  f32
    float* out = (float*)d_out;              // At2 (8,1024,1024) ++ xg (8,1024,128)

    extract_kernel<<<(B * N) / 256, 256>>>(x);
    select_kernel<<<B, 512>>>();
    rank_kernel<<<B * 8, 128>>>();
    gather_kernel<<<B * (GS / 8), 512>>>(A, x, out);
}